// round 5
// baseline (speedup 1.0000x reference)
#include <cuda_runtime.h>

#define B 2
#define N 2048
#define C 768
#define CG 192           // C/4 float4 groups
#define G 128            // grid size (co-resident, 1 wave)
#define T 256            // block size

__device__ float4 g_part[B][64][CG];    // P1 output: 64 partial colsums per batch
__device__ float  g_s[B][C];            // s_b = sum_n X[b,n,:]
__device__ float  g_u[B][C];            // u_b = Wk s_b
__device__ float4 g_vpart[B][G][CG];    // P4 output: per-CTA partials of v
__device__ float  g_v[B][C];            // v_b = Wq^T u_b
__device__ unsigned g_bar[8];           // monotonic barrier counters (zero-init)

__device__ __forceinline__ float4 f4add(float4 a, float4 b) {
    return make_float4(a.x + b.x, a.y + b.y, a.z + b.z, a.w + b.w);
}
__device__ __forceinline__ float4 f4fma(float4 a, float s, float4 acc) {
    return make_float4(fmaf(a.x, s, acc.x), fmaf(a.y, s, acc.y),
                       fmaf(a.z, s, acc.z), fmaf(a.w, s, acc.w));
}

// Grid-wide barrier. Monotonic counter: each launch adds exactly G arrivals per
// slot, so (old/G+1)*G is the release target — no reset across graph replays.
// Hard spin on the L2 line (no nanosleep): poll interval = L2 round-trip.
__device__ __forceinline__ void grid_barrier(int i) {
    __threadfence();                    // release: order this thread's writes
    __syncthreads();
    if (threadIdx.x == 0) {
        unsigned old = atomicAdd(&g_bar[i], 1u);
        unsigned target = (old / G + 1u) * G;
        volatile unsigned* p = &g_bar[i];
        while (*p < target) { }
        __threadfence();                // acquire
    }
    __syncthreads();
}

__global__ void __launch_bounds__(T, 1)
fused_att_scores(const float4* __restrict__ X4, const float4* __restrict__ W4,
                 float* __restrict__ out) {
    __shared__ float4 sh[4 * CG];   // 12 KB, reused across phases
    const int ct  = blockIdx.x;
    const int tid = threadIdx.x;

    // ---- P1: partial column sums of X. CTA (b, chunk) covers 32 rows.
    // 256 threads = 64 cg-quarters x 4 row-slices; 3 accumulators each (24 loads).
    {
        int b = ct & 1, chunk = ct >> 1;              // 64 chunks per batch
        int cgq = tid & 63, rs = tid >> 6;            // rs in [0,4)
        const float4* p = X4 + ((size_t)b * N + chunk * 32 + rs * 8) * CG + cgq;
        float4 a0 = make_float4(0.f, 0.f, 0.f, 0.f);
        float4 a1 = a0, a2 = a0;
#pragma unroll
        for (int r = 0; r < 8; ++r) {
            const float4* q = p + (size_t)r * CG;
            a0 = f4add(a0, q[0]);
            a1 = f4add(a1, q[64]);
            a2 = f4add(a2, q[128]);
        }
        sh[rs * CG + cgq]       = a0;
        sh[rs * CG + cgq + 64]  = a1;
        sh[rs * CG + cgq + 128] = a2;
        __syncthreads();
        if (tid < CG) {
            float4 v = f4add(f4add(sh[tid], sh[CG + tid]),
                             f4add(sh[2 * CG + tid], sh[3 * CG + tid]));
            g_part[b][chunk][tid] = v;
        }
    }
    grid_barrier(0);

    // ---- P2: reduce 64 partials -> s. 16 CTAs: (b, slice of 24 cgs). ----
    if (ct < 16) {
        int b = ct & 1, qs = ct >> 1;                 // qs in [0,8)
        int base = qs * 24;
        if (tid < 192) {
            int gi = tid % 24, sl = tid / 24;         // 8 slices of 8 partials
            float4 acc = make_float4(0.f, 0.f, 0.f, 0.f);
#pragma unroll
            for (int k = 0; k < 8; ++k)
                acc = f4add(acc, g_part[b][sl * 8 + k][base + gi]);
            sh[tid] = acc;
        }
        __syncthreads();
        if (tid < 24) {
            float4 v = make_float4(0.f, 0.f, 0.f, 0.f);
#pragma unroll
            for (int s = 0; s < 8; ++s)
                v = f4add(v, sh[s * 24 + tid]);
            ((float4*)g_s[b])[base + tid] = v;
        }
    }
    grid_barrier(1);

    // ---- P3: u = Wk s (both batches). CTA handles 6 j-rows, 1 warp each. ----
    {
        for (int i = tid; i < 2 * CG; i += T)         // stage s (both batches)
            sh[i] = (i < CG) ? ((const float4*)g_s[0])[i]
                             : ((const float4*)g_s[1])[i - CG];
        __syncthreads();
        int wid = tid >> 5, lane = tid & 31;
        if (wid < 6) {
            int j = ct * 6 + wid;
            const float4* row = W4 + (size_t)(C + j) * CG;   // Wk half
            float a0 = 0.f, a1 = 0.f;
#pragma unroll
            for (int k = 0; k < 6; ++k) {
                int c4 = lane + k * 32;
                float4 w  = row[c4];
                float4 v0 = sh[c4];
                float4 v1 = sh[CG + c4];
                a0 += w.x * v0.x + w.y * v0.y + w.z * v0.z + w.w * v0.w;
                a1 += w.x * v1.x + w.y * v1.y + w.z * v1.z + w.w * v1.w;
            }
#pragma unroll
            for (int o = 16; o > 0; o >>= 1) {
                a0 += __shfl_down_sync(0xFFFFFFFFu, a0, o);
                a1 += __shfl_down_sync(0xFFFFFFFFu, a1, o);
            }
            if (lane == 0) { g_u[0][j] = a0; g_u[1][j] = a1; }
        }
    }
    grid_barrier(2);

    // ---- P4: vpart = Wq^T u partials. CTA handles 6 j-rows over all cols. ----
    {
        int j0 = ct * 6;
        if (tid < CG) {
            float4 a0 = make_float4(0.f, 0.f, 0.f, 0.f);
            float4 a1 = make_float4(0.f, 0.f, 0.f, 0.f);
#pragma unroll
            for (int jj = 0; jj < 6; ++jj) {
                float4 w = W4[(size_t)(j0 + jj) * CG + tid]; // Wq half
                a0 = f4fma(w, g_u[0][j0 + jj], a0);
                a1 = f4fma(w, g_u[1][j0 + jj], a1);
            }
            g_vpart[0][ct][tid] = a0;
            g_vpart[1][ct][tid] = a1;
        }
    }
    grid_barrier(3);

    // ---- P5: reduce G partials -> v. 16 CTAs: (b, slice of 24 cgs). ----
    if (ct < 16) {
        int b = ct & 1, qs = ct >> 1;
        int base = qs * 24;
        if (tid < 192) {
            int gi = tid % 24, sl = tid / 24;         // 8 slices of 16 partials
            float4 acc = make_float4(0.f, 0.f, 0.f, 0.f);
#pragma unroll
            for (int k = 0; k < 16; ++k)
                acc = f4add(acc, g_vpart[b][sl * 16 + k][base + gi]);
            sh[tid] = acc;
        }
        __syncthreads();
        if (tid < 24) {
            float4 v = make_float4(0.f, 0.f, 0.f, 0.f);
#pragma unroll
            for (int s = 0; s < 8; ++s)
                v = f4add(v, sh[s * 24 + tid]);
            ((float4*)g_v[b])[base + tid] = v;
        }
    }
    grid_barrier(4);

    // ---- P6: scores[b,n] = 0.125 * X[b,n,:] . v[b]. CTA: 32 rows, 8 warps. ----
    {
        int b = ct & 1, rowblock = ct >> 1;           // 64 rowblocks of 32 rows
        if (tid < CG) sh[tid] = ((const float4*)g_v[b])[tid];
        __syncthreads();
        int wid = tid >> 5, lane = tid & 31;
        int nbase = rowblock * 32 + wid * 4;
        float a[4];
#pragma unroll
        for (int r = 0; r < 4; ++r) {
            const float4* x = X4 + ((size_t)b * N + (nbase + r)) * CG;
            float acc = 0.f;
#pragma unroll
            for (int k = 0; k < 6; ++k) {
                int c4 = lane + k * 32;
                float4 xv = x[c4];
                float4 vv = sh[c4];
                acc += xv.x * vv.x + xv.y * vv.y + xv.z * vv.z + xv.w * vv.w;
            }
            a[r] = acc;
        }
#pragma unroll
        for (int o = 16; o > 0; o >>= 1) {
#pragma unroll
            for (int r = 0; r < 4; ++r)
                a[r] += __shfl_down_sync(0xFFFFFFFFu, a[r], o);
        }
        if (lane == 0) {
#pragma unroll
            for (int r = 0; r < 4; ++r)
                out[b * N + nbase + r] = 0.125f * a[r];
        }
    }
}

extern "C" void kernel_launch(void* const* d_in, const int* in_sizes, int n_in,
                              void* d_out, int out_size) {
    const float4* X4 = (const float4*)d_in[0];  // [2, 2048, 768] f32
    const float4* W4 = (const float4*)d_in[1];  // [1536, 768] f32
    float* out = (float*)d_out;                 // [2, 2048] f32
    (void)in_sizes; (void)n_in; (void)out_size;

    fused_att_scores<<<G, T>>>(X4, W4, out);
}

// round 6
// speedup vs baseline: 1.1518x; 1.1518x over previous
#include <cuda_runtime.h>

#define B 2
#define N 2048
#define C 768
#define CG 192           // C/4 float4 groups
#define G 256            // grid size: 2 CTAs/SM, all co-resident (<= 296)
#define T 256            // block size

__device__ float4 g_part[B][128][CG];   // P1: 128 partial colsums per batch
__device__ float  g_s[B][C];            // s_b = sum_n X[b,n,:]
__device__ float4 g_vpart[B][G][CG];    // P3: per-CTA partials of v
__device__ float  g_v[B][C];            // v_b = Wq^T Wk s_b
__device__ unsigned g_bar[8];           // monotonic barrier counters (zero-init)

__device__ __forceinline__ float4 f4add(float4 a, float4 b) {
    return make_float4(a.x + b.x, a.y + b.y, a.z + b.z, a.w + b.w);
}
__device__ __forceinline__ float4 f4fma(float4 a, float s, float4 acc) {
    return make_float4(fmaf(a.x, s, acc.x), fmaf(a.y, s, acc.y),
                       fmaf(a.z, s, acc.z), fmaf(a.w, s, acc.w));
}

// Grid-wide barrier. Monotonic counter: each launch adds exactly G arrivals per
// slot, so (old/G+1)*G is the release target — no reset across graph replays.
__device__ __forceinline__ void grid_barrier(int i) {
    __threadfence();                    // release
    __syncthreads();
    if (threadIdx.x == 0) {
        unsigned old = atomicAdd(&g_bar[i], 1u);
        unsigned target = (old / G + 1u) * G;
        volatile unsigned* p = &g_bar[i];
        while (*p < target) { }
        __threadfence();                // acquire
    }
    __syncthreads();
}

__global__ void __launch_bounds__(T, 2)
fused_att_scores(const float4* __restrict__ X4, const float4* __restrict__ W4,
                 float* __restrict__ out) {
    __shared__ float4 sh[4 * CG];       // 12.3 KB, reused across phases
    __shared__ float u0s[4], u1s[4];
    const int ct  = blockIdx.x;
    const int tid = threadIdx.x;

    // ---- P1: partial column sums of X. CTA (b, chunk) covers 16 rows.
    // 256 thr = 64 cg-quarters x 4 row-slices; 3 accumulators, 12 loads each.
    {
        int b = ct & 1, chunk = ct >> 1;              // 128 chunks per batch
        int cgq = tid & 63, rs = tid >> 6;            // rs in [0,4)
        const float4* p = X4 + ((size_t)b * N + chunk * 16 + rs * 4) * CG + cgq;
        float4 a0 = make_float4(0.f, 0.f, 0.f, 0.f);
        float4 a1 = a0, a2 = a0;
#pragma unroll
        for (int r = 0; r < 4; ++r) {
            const float4* q = p + (size_t)r * CG;
            a0 = f4add(a0, q[0]);
            a1 = f4add(a1, q[64]);
            a2 = f4add(a2, q[128]);
        }
        sh[rs * CG + cgq]       = a0;
        sh[rs * CG + cgq + 64]  = a1;
        sh[rs * CG + cgq + 128] = a2;
        __syncthreads();
        if (tid < CG) {
            float4 v = f4add(f4add(sh[tid], sh[CG + tid]),
                             f4add(sh[2 * CG + tid], sh[3 * CG + tid]));
            g_part[b][chunk][tid] = v;
        }
    }
    grid_barrier(0);

    // ---- P2: reduce 128 partials -> s. 32 CTAs: (b, slice of 12 cgs). ----
    if (ct < 32) {
        int b = ct & 1, qs = ct >> 1;                 // qs in [0,16)
        int base = qs * 12;
        if (tid < 192) {
            int gi = tid % 12, sl = tid / 12;         // 16 slices of 8 partials
            float4 acc = make_float4(0.f, 0.f, 0.f, 0.f);
#pragma unroll
            for (int k = 0; k < 8; ++k)
                acc = f4add(acc, g_part[b][sl * 8 + k][base + gi]);
            sh[tid] = acc;
        }
        __syncthreads();
        if (tid < 12) {
            float4 v = make_float4(0.f, 0.f, 0.f, 0.f);
#pragma unroll
            for (int s = 0; s < 16; ++s)
                v = f4add(v, sh[s * 12 + tid]);
            ((float4*)g_s[b])[base + tid] = v;
        }
    }
    grid_barrier(1);

    // ---- P3 (fused): for 3 j-rows: u_j = Wk_j . s, then vpart += u_j * Wq_j.
    {
        for (int i = tid; i < 2 * CG; i += T)         // stage s (both batches)
            sh[i] = (i < CG) ? ((const float4*)g_s[0])[i]
                             : ((const float4*)g_s[1])[i - CG];
        __syncthreads();
        int wid = tid >> 5, lane = tid & 31;
        int j0 = ct * 3;
        if (wid < 3) {
            int j = j0 + wid;
            const float4* row = W4 + (size_t)(C + j) * CG;   // Wk half
            float a0 = 0.f, a1 = 0.f;
#pragma unroll
            for (int k = 0; k < 6; ++k) {
                int c4 = lane + k * 32;
                float4 w  = row[c4];
                float4 v0 = sh[c4];
                float4 v1 = sh[CG + c4];
                a0 += w.x * v0.x + w.y * v0.y + w.z * v0.z + w.w * v0.w;
                a1 += w.x * v1.x + w.y * v1.y + w.z * v1.z + w.w * v1.w;
            }
#pragma unroll
            for (int o = 16; o > 0; o >>= 1) {
                a0 += __shfl_down_sync(0xFFFFFFFFu, a0, o);
                a1 += __shfl_down_sync(0xFFFFFFFFu, a1, o);
            }
            if (lane == 0) { u0s[wid] = a0; u1s[wid] = a1; }
        }
        __syncthreads();
        if (tid < CG) {
            float4 a0 = make_float4(0.f, 0.f, 0.f, 0.f);
            float4 a1 = make_float4(0.f, 0.f, 0.f, 0.f);
#pragma unroll
            for (int jj = 0; jj < 3; ++jj) {
                float4 w = W4[(size_t)(j0 + jj) * CG + tid]; // Wq half
                a0 = f4fma(w, u0s[jj], a0);
                a1 = f4fma(w, u1s[jj], a1);
            }
            g_vpart[0][ct][tid] = a0;
            g_vpart[1][ct][tid] = a1;
        }
    }
    grid_barrier(2);

    // ---- P4: reduce G partials -> v. 32 CTAs: (b, slice of 12 cgs). ----
    if (ct < 32) {
        int b = ct & 1, qs = ct >> 1;
        int base = qs * 12;
        if (tid < 192) {
            int gi = tid % 12, sl = tid / 12;         // 16 slices of 16 partials
            float4 acc = make_float4(0.f, 0.f, 0.f, 0.f);
#pragma unroll
            for (int k = 0; k < 16; ++k)
                acc = f4add(acc, g_vpart[b][sl * 16 + k][base + gi]);
            sh[tid] = acc;
        }
        __syncthreads();
        if (tid < 12) {
            float4 v = make_float4(0.f, 0.f, 0.f, 0.f);
#pragma unroll
            for (int s = 0; s < 16; ++s)
                v = f4add(v, sh[s * 12 + tid]);
            ((float4*)g_v[b])[base + tid] = v;
        }
    }
    grid_barrier(3);

    // ---- P5: scores[b,n] = 0.125 * X[b,n,:] . v[b]. CTA: 16 rows, 8 warps. ----
    {
        int b = ct & 1, rowblock = ct >> 1;           // 128 rowblocks of 16 rows
        if (tid < CG) sh[tid] = ((const float4*)g_v[b])[tid];
        __syncthreads();
        int wid = tid >> 5, lane = tid & 31;
        int nbase = rowblock * 16 + wid * 2;
        float a[2];
#pragma unroll
        for (int r = 0; r < 2; ++r) {
            const float4* x = X4 + ((size_t)b * N + (nbase + r)) * CG;
            float acc = 0.f;
#pragma unroll
            for (int k = 0; k < 6; ++k) {
                int c4 = lane + k * 32;
                float4 xv = x[c4];
                float4 vv = sh[c4];
                acc += xv.x * vv.x + xv.y * vv.y + xv.z * vv.z + xv.w * vv.w;
            }
            a[r] = acc;
        }
#pragma unroll
        for (int o = 16; o > 0; o >>= 1) {
#pragma unroll
            for (int r = 0; r < 2; ++r)
                a[r] += __shfl_down_sync(0xFFFFFFFFu, a[r], o);
        }
        if (lane == 0) {
#pragma unroll
            for (int r = 0; r < 2; ++r)
                out[b * N + nbase + r] = 0.125f * a[r];
        }
    }
}

extern "C" void kernel_launch(void* const* d_in, const int* in_sizes, int n_in,
                              void* d_out, int out_size) {
    const float4* X4 = (const float4*)d_in[0];  // [2, 2048, 768] f32
    const float4* W4 = (const float4*)d_in[1];  // [1536, 768] f32
    float* out = (float*)d_out;                 // [2, 2048] f32
    (void)in_sizes; (void)n_in; (void)out_size;

    fused_att_scores<<<G, T>>>(X4, W4, out);
}